// round 9
// baseline (speedup 1.0000x reference)
#include <cuda_runtime.h>

#define HH 512
#define WW 512
#define CHN 6
#define BATCH 2
#define EPS_F 1e-6f

__device__ __forceinline__ int refl(int i, int n) {
    if (i < 0) i = -i;
    if (i >= n) i = 2 * n - 2 - i;
    return i;
}

// upper-triangle (i<=j) linear index into 21-entry array
__device__ __forceinline__ constexpr int IU(int i, int j) {
    return i * 6 - i * (i - 1) / 2 + (j - i);
}
// lower-triangle (i>=j) linear index into 21-entry array
__device__ __forceinline__ constexpr int IL(int i, int j) {
    return i * (i + 1) / 2 + j;
}

// Per-pixel CCA directly from raw window sums.
__device__ __forceinline__ float cca6(const float* sx, const float* sy,
                                      const float* sxx, const float* syy,
                                      const float* sxy, float inv_n) {
    float xm[6], ym[6];
#pragma unroll
    for (int i = 0; i < 6; i++) { xm[i] = sx[i] * inv_n; ym[i] = sy[i] * inv_n; }

    // Cholesky of cxx and cyy (lower L, 21 entries each); rsqrt-based.
    float Lx[21], Ly[21], ivx[6], ivy[6];
#pragma unroll
    for (int j = 0; j < 6; j++) {
        float dx = fmaf(-xm[j], xm[j], sxx[IU(j, j)] * inv_n) + EPS_F;
        float dy = fmaf(-ym[j], ym[j], syy[IU(j, j)] * inv_n) + EPS_F;
#pragma unroll
        for (int t = 0; t < j; t++) {
            dx = fmaf(-Lx[IL(j, t)], Lx[IL(j, t)], dx);
            dy = fmaf(-Ly[IL(j, t)], Ly[IL(j, t)], dy);
        }
        float rx = rsqrtf(dx), ry = rsqrtf(dy);
        ivx[j] = rx;
        ivy[j] = ry;
        Lx[IL(j, j)] = dx * rx;
        Ly[IL(j, j)] = dy * ry;
#pragma unroll
        for (int i = j + 1; i < 6; i++) {
            float vx = fmaf(-xm[j], xm[i], sxx[IU(j, i)] * inv_n);
            float vy = fmaf(-ym[j], ym[i], syy[IU(j, i)] * inv_n);
#pragma unroll
            for (int t = 0; t < j; t++) {
                vx = fmaf(-Lx[IL(i, t)], Lx[IL(j, t)], vx);
                vy = fmaf(-Ly[IL(i, t)], Ly[IL(j, t)], vy);
            }
            Lx[IL(i, j)] = vx * ivx[j];
            Ly[IL(i, j)] = vy * ivy[j];
        }
    }

    // M = Lx^{-1} * cxy ; only upper triangle (i<=j) needed downstream.
    float MN[21];
#pragma unroll
    for (int j = 0; j < 6; j++) {
#pragma unroll
        for (int i = 0; i <= j; i++) {
            float v = fmaf(-xm[i], ym[j], sxy[i * 6 + j] * inv_n);
#pragma unroll
            for (int t = 0; t < i; t++) v = fmaf(-Lx[IL(i, t)], MN[IU(t, j)], v);
            MN[IU(i, j)] = v * ivx[i];
        }
    }
    // N = M * Ly^{-1}, in place (back-substitution per row).
    float sim = 0.f;
#pragma unroll
    for (int i = 0; i < 6; i++) {
#pragma unroll
        for (int j = 5; j >= i; j--) {
            float v = MN[IU(i, j)];
#pragma unroll
            for (int t = j + 1; t < 6; t++) v = fmaf(-MN[IU(i, t)], Ly[IL(t, j)], v);
            v *= ivy[j];
            MN[IU(i, j)] = v;
            if (j == i) sim += fabsf(v);
        }
    }
    return sim * (1.0f / 6.0f);
}

// Skewed column map: phys(col) = col + (col>>2).
// With PS=56 float2 (112 words === 16 mod 32), every warp-phase of the window
// LDS.64 hits 16 distinct bank pairs -> conflict-free (lane-dependence = 5*txg).
__device__ __forceinline__ int skew(int col) { return col + (col >> 2); }

// Compile-time-K body. PS shared (56) so both paths are conflict-free.
template <int K, int TILE, int NTX>
__device__ __forceinline__ void cca_body(
    const float* __restrict__ x, const float* __restrict__ y,
    float* __restrict__ out, int b, int ri, float2* sm) {
    constexpr int R = (K - 1) / 2;
    constexpr int PH = TILE + K - 1;
    constexpr int PW = PH;
    constexpr int PS = 56;        // row stride in float2 (see skew comment)
    constexpr int CHS = PH * PS;  // channel stride (float2 elems)
    constexpr int RPP = TILE / NTX;
    constexpr float INV_N = 1.0f / (float)(K * K);
    constexpr int NTHR = TILE * NTX;
    constexpr int NELEM = 6 * PH * PW;
    constexpr int NITER = (NELEM + NTHR - 1) / NTHR;
    constexpr int STEPR = NTHR / PW;
    constexpr int STEPC = NTHR % PW;

    const int tx0 = blockIdx.x * TILE;
    const int ty0 = blockIdx.y * TILE;
    const int tid = threadIdx.x;

    // division-free cooperative load of padded 6-channel (x,y)-packed tile
    {
        int c = 0;
        int row = tid / PW;        // one compile-time-constant division
        int col = tid - row * PW;
#pragma unroll 1
        for (int it = 0; it < NITER; ++it) {
            if (c < 6) {
                int gy = refl(ty0 - R + row, HH);
                int gx = refl(tx0 - R + col, WW);
                size_t gidx = ((size_t)(b * CHN + c) * HH + gy) * WW + gx;
                float2 v;
                v.x = x[gidx];
                v.y = y[gidx];
                sm[c * CHS + row * PS + skew(col)] = v;
            }
            col += STEPC;
            row += STEPR;
            if (col >= PW) { col -= PW; row += 1; }
            if (row >= PH) { row -= PH; c += 1; }
        }
    }
    __syncthreads();

    const int txg = tid & (NTX - 1);
    const int ty = tid / NTX;      // output row within tile
    const int c0 = txg * RPP;      // first output col within tile (logical)

    float sx[6], sy[6], sxx[21], syy[21], sxy[36];
#pragma unroll
    for (int i = 0; i < 6; i++) { sx[i] = 0.f; sy[i] = 0.f; }
#pragma unroll
    for (int i = 0; i < 21; i++) { sxx[i] = 0.f; syy[i] = 0.f; }
#pragma unroll
    for (int i = 0; i < 36; i++) sxy[i] = 0.f;

    auto accumAdd = [&](const float2* p) {
        float xv[6], yv[6];
#pragma unroll
        for (int c = 0; c < 6; c++) {
            float2 v = p[c * CHS];
            xv[c] = v.x;
            yv[c] = v.y;
        }
#pragma unroll
        for (int i = 0; i < 6; i++) { sx[i] += xv[i]; sy[i] += yv[i]; }
        int t = 0;
#pragma unroll
        for (int i = 0; i < 6; i++)
#pragma unroll
            for (int j = i; j < 6; j++, t++) {
                sxx[t] = fmaf(xv[i], xv[j], sxx[t]);
                syy[t] = fmaf(yv[i], yv[j], syy[t]);
            }
#pragma unroll
        for (int i = 0; i < 6; i++)
#pragma unroll
            for (int j = 0; j < 6; j++)
                sxy[i * 6 + j] = fmaf(xv[i], yv[j], sxy[i * 6 + j]);
    };
    auto accumSub = [&](const float2* p) {
        float xv[6], yv[6];
#pragma unroll
        for (int c = 0; c < 6; c++) {
            float2 v = p[c * CHS];
            xv[c] = v.x;
            yv[c] = v.y;
        }
#pragma unroll
        for (int i = 0; i < 6; i++) { sx[i] -= xv[i]; sy[i] -= yv[i]; }
        int t = 0;
#pragma unroll
        for (int i = 0; i < 6; i++)
#pragma unroll
            for (int j = i; j < 6; j++, t++) {
                sxx[t] = fmaf(-xv[i], xv[j], sxx[t]);
                syy[t] = fmaf(-yv[i], yv[j], syy[t]);
            }
#pragma unroll
        for (int i = 0; i < 6; i++)
#pragma unroll
            for (int j = 0; j < 6; j++)
                sxy[i * 6 + j] = fmaf(-xv[i], yv[j], sxy[i * 6 + j]);
    };

    // thread base: row = ty, col = c0 (phys = 5*txg since c0 = 4*txg)
    const float2* pbase = sm + ty * PS + skew(c0);

    // initial full window for first pixel (col-outer, row pointer induction)
#pragma unroll 1
    for (int q = 0; q < K; ++q) {
        const float2* pr = pbase + (q + (q >> 2));
#pragma unroll 1
        for (int r = 0; r < K; ++r) {
            accumAdd(pr);
            pr += PS;
        }
    }

    const int gy = ty0 + ty;
    {
        float sim = cca6(sx, sy, sxx, syy, sxy, INV_N);
        out[(((size_t)b * HH + gy) * WW + (tx0 + c0)) * 2 + ri] = sim;
    }

#pragma unroll 1
    for (int p = 1; p < RPP; ++p) {
        const int cs = p - 1, ca = p - 1 + K;
        const float2* ps_ = pbase + (cs + (cs >> 2));
        const float2* pa_ = pbase + (ca + (ca >> 2));
#pragma unroll 1
        for (int r = 0; r < K; ++r) {
            accumSub(ps_);
            accumAdd(pa_);
            ps_ += PS;
            pa_ += PS;
        }
        float sim = cca6(sx, sy, sxx, syy, sxy, INV_N);
        out[(((size_t)b * HH + gy) * WW + (tx0 + c0 + p)) * 2 + ri] = sim;
    }
}

// Single merged launch. z in {0,1}: K=9 (expensive, dispatched first);
// z in {2,3}: K=5 (cheap tail).
template <int TILE, int NTX>
__global__ __launch_bounds__(TILE* NTX, 2) void cca_kernel(
    const float* __restrict__ x, const float* __restrict__ y,
    float* __restrict__ out) {
    extern __shared__ float2 sm[];
    const int z = blockIdx.z;
    if (z < 2)
        cca_body<9, TILE, NTX>(x, y, out, z, 1, sm);
    else
        cca_body<5, TILE, NTX>(x, y, out, z - 2, 0, sm);
}

extern "C" void kernel_launch(void* const* d_in, const int* in_sizes, int n_in,
                              void* d_out, int out_size) {
    (void)in_sizes; (void)n_in; (void)out_size;
    const float* x = (const float*)d_in[0];
    const float* y = (const float*)d_in[1];
    float* out = (float*)d_out;

    constexpr int TILE = 32, NTX = 8;
    dim3 grid(WW / TILE, HH / TILE, BATCH * 2);
    dim3 block(TILE * NTX);

    // K=9 path: 6 planes of 40 rows x 56 float2 stride
    constexpr int SMX = 6 * 40 * 56 * 8;

    cudaFuncSetAttribute(cca_kernel<TILE, NTX>,
                         cudaFuncAttributeMaxDynamicSharedMemorySize, SMX);

    cca_kernel<TILE, NTX><<<grid, block, SMX>>>(x, y, out);
}

// round 11
// speedup vs baseline: 1.1230x; 1.1230x over previous
#include <cuda_runtime.h>

#define HH 512
#define WW 512
#define CHN 6
#define BATCH 2
#define EPS_F 1e-6f

__device__ __forceinline__ int refl(int i, int n) {
    if (i < 0) i = -i;
    if (i >= n) i = 2 * n - 2 - i;
    return i;
}

// upper-triangle (i<=j) linear index into 21-entry array
__device__ __forceinline__ constexpr int IU(int i, int j) {
    return i * 6 - i * (i - 1) / 2 + (j - i);
}
// lower-triangle (i>=j) linear index into 21-entry array
__device__ __forceinline__ constexpr int IL(int i, int j) {
    return i * (i + 1) / 2 + j;
}

// Per-pixel CCA directly from raw window sums. Covariance entries are
// materialized inline at their single use (no cxx/cyy/cxy register arrays).
// sxx/syy upper-tri (i<=j), sxy full row-major [i*6+j].
__device__ __forceinline__ float cca6(const float* sx, const float* sy,
                                      const float* sxx, const float* syy,
                                      const float* sxy, float inv_n) {
    float xm[6], ym[6];
#pragma unroll
    for (int i = 0; i < 6; i++) { xm[i] = sx[i] * inv_n; ym[i] = sy[i] * inv_n; }

    // Cholesky of cxx and cyy (lower L, 21 entries each); rsqrt-based.
    float Lx[21], Ly[21], ivx[6], ivy[6];
#pragma unroll
    for (int j = 0; j < 6; j++) {
        float dx = fmaf(-xm[j], xm[j], sxx[IU(j, j)] * inv_n) + EPS_F;
        float dy = fmaf(-ym[j], ym[j], syy[IU(j, j)] * inv_n) + EPS_F;
#pragma unroll
        for (int t = 0; t < j; t++) {
            dx = fmaf(-Lx[IL(j, t)], Lx[IL(j, t)], dx);
            dy = fmaf(-Ly[IL(j, t)], Ly[IL(j, t)], dy);
        }
        float rx = rsqrtf(dx), ry = rsqrtf(dy);
        ivx[j] = rx;
        ivy[j] = ry;
        Lx[IL(j, j)] = dx * rx;
        Ly[IL(j, j)] = dy * ry;
#pragma unroll
        for (int i = j + 1; i < 6; i++) {
            float vx = fmaf(-xm[j], xm[i], sxx[IU(j, i)] * inv_n);
            float vy = fmaf(-ym[j], ym[i], syy[IU(j, i)] * inv_n);
#pragma unroll
            for (int t = 0; t < j; t++) {
                vx = fmaf(-Lx[IL(i, t)], Lx[IL(j, t)], vx);
                vy = fmaf(-Ly[IL(i, t)], Ly[IL(j, t)], vy);
            }
            Lx[IL(i, j)] = vx * ivx[j];
            Ly[IL(i, j)] = vy * ivy[j];
        }
    }

    // M = Lx^{-1} * cxy ; only upper triangle (i<=j) needed downstream.
    float MN[21];
#pragma unroll
    for (int j = 0; j < 6; j++) {
#pragma unroll
        for (int i = 0; i <= j; i++) {
            float v = fmaf(-xm[i], ym[j], sxy[i * 6 + j] * inv_n);
#pragma unroll
            for (int t = 0; t < i; t++) v = fmaf(-Lx[IL(i, t)], MN[IU(t, j)], v);
            MN[IU(i, j)] = v * ivx[i];
        }
    }
    // N = M * Ly^{-1}, in place (back-substitution per row).
    float sim = 0.f;
#pragma unroll
    for (int i = 0; i < 6; i++) {
#pragma unroll
        for (int j = 5; j >= i; j--) {
            float v = MN[IU(i, j)];
#pragma unroll
            for (int t = j + 1; t < 6; t++) v = fmaf(-MN[IU(i, t)], Ly[IL(t, j)], v);
            v *= ivy[j];
            MN[IU(i, j)] = v;
            if (j == i) sim += fabsf(v);
        }
    }
    return sim * (1.0f / 6.0f);
}

// Skewed column map: phys(col) = col + (col>>2), row stride PS=56 float2
// (112 words === 16 mod 32). For the warp's window access (txg = lane&7,
// row = lane>>3): word addr = 16*(lane>>3) + 10*txg + const (mod 32);
// each 16-lane phase covers all 32 banks exactly once -> conflict-free LDS.64.
__device__ __forceinline__ int skew(int col) { return col + (col >> 2); }

// Compile-time-K body. All plane strides constexpr -> LDS immediate offsets.
template <int K, int TILE, int NTX>
__device__ __forceinline__ void cca_body(
    const float* __restrict__ x, const float* __restrict__ y,
    float* __restrict__ out, int b, int ri, float2* sm) {
    constexpr int R = (K - 1) / 2;
    constexpr int PH = TILE + K - 1;
    constexpr int PW = PH;
    constexpr int PS = 56;       // skewed row stride (see skew comment)
    constexpr int CHS = PH * PS; // channel stride (float2 elems), constexpr
    constexpr int RPP = TILE / NTX;
    constexpr float INV_N = 1.0f / (float)(K * K);

    const int tx0 = blockIdx.x * TILE;
    const int ty0 = blockIdx.y * TILE;
    const int tid = threadIdx.x;

    // cooperative load of padded 6-channel (x,y)-packed tile
    // (independent iterations -> compiler unrolls -> high LDG MLP)
    for (int idx = tid; idx < 6 * PH * PW; idx += TILE * NTX) {
        int c = idx / (PH * PW);        // constexpr divisor -> mul-by-recip
        int rem = idx - c * (PH * PW);
        int row = rem / PW;
        int col = rem - row * PW;
        int gy = refl(ty0 - R + row, HH);
        int gx = refl(tx0 - R + col, WW);
        size_t gidx = ((size_t)(b * CHN + c) * HH + gy) * WW + gx;
        float2 v;
        v.x = x[gidx];
        v.y = y[gidx];
        sm[c * CHS + row * PS + skew(col)] = v;
    }
    __syncthreads();

    const int txg = tid & (NTX - 1);
    const int ty = tid / NTX;      // output row within tile
    const int c0 = txg * RPP;      // first output col within tile (logical)

    float sx[6], sy[6], sxx[21], syy[21], sxy[36];
#pragma unroll
    for (int i = 0; i < 6; i++) { sx[i] = 0.f; sy[i] = 0.f; }
#pragma unroll
    for (int i = 0; i < 21; i++) { sxx[i] = 0.f; syy[i] = 0.f; }
#pragma unroll
    for (int i = 0; i < 36; i++) sxy[i] = 0.f;

    auto loadvals = [&](int row, int col, float* xv, float* yv) {
        const float2* p = sm + row * PS + skew(col);
#pragma unroll
        for (int c = 0; c < 6; c++) {
            float2 v = p[c * CHS];  // constexpr offset -> LDS immediate
            xv[c] = v.x;
            yv[c] = v.y;
        }
    };
    auto accumAdd = [&](int row, int col) {
        float xv[6], yv[6];
        loadvals(row, col, xv, yv);
#pragma unroll
        for (int i = 0; i < 6; i++) { sx[i] += xv[i]; sy[i] += yv[i]; }
        int t = 0;
#pragma unroll
        for (int i = 0; i < 6; i++)
#pragma unroll
            for (int j = i; j < 6; j++, t++) {
                sxx[t] = fmaf(xv[i], xv[j], sxx[t]);
                syy[t] = fmaf(yv[i], yv[j], syy[t]);
            }
#pragma unroll
        for (int i = 0; i < 6; i++)
#pragma unroll
            for (int j = 0; j < 6; j++)
                sxy[i * 6 + j] = fmaf(xv[i], yv[j], sxy[i * 6 + j]);
    };
    auto accumSub = [&](int row, int col) {
        float xv[6], yv[6];
        loadvals(row, col, xv, yv);
#pragma unroll
        for (int i = 0; i < 6; i++) { sx[i] -= xv[i]; sy[i] -= yv[i]; }
        int t = 0;
#pragma unroll
        for (int i = 0; i < 6; i++)
#pragma unroll
            for (int j = i; j < 6; j++, t++) {
                sxx[t] = fmaf(-xv[i], xv[j], sxx[t]);
                syy[t] = fmaf(-yv[i], yv[j], syy[t]);
            }
#pragma unroll
        for (int i = 0; i < 6; i++)
#pragma unroll
            for (int j = 0; j < 6; j++)
                sxy[i * 6 + j] = fmaf(-xv[i], yv[j], sxy[i * 6 + j]);
    };

    // initial full window for first pixel
#pragma unroll 1
    for (int r = 0; r < K; ++r)
#pragma unroll 1
        for (int c = 0; c < K; ++c) accumAdd(ty + r, c0 + c);

    const int gy = ty0 + ty;
    {
        float sim = cca6(sx, sy, sxx, syy, sxy, INV_N);
        out[(((size_t)b * HH + gy) * WW + (tx0 + c0)) * 2 + ri] = sim;
    }

#pragma unroll 1
    for (int p = 1; p < RPP; ++p) {
#pragma unroll 1
        for (int r = 0; r < K; ++r) {
            accumSub(ty + r, c0 + p - 1);
            accumAdd(ty + r, c0 + p - 1 + K);
        }
        float sim = cca6(sx, sy, sxx, syy, sxy, INV_N);
        out[(((size_t)b * HH + gy) * WW + (tx0 + c0 + p)) * 2 + ri] = sim;
    }
}

// Single merged launch; blockIdx.z encodes (batch, radius). Uniform per-CTA
// branch dispatches to a compile-time-K body.
template <int TILE, int NTX>
__global__ __launch_bounds__(TILE* NTX, 2) void cca_kernel(
    const float* __restrict__ x, const float* __restrict__ y,
    float* __restrict__ out) {
    extern __shared__ float2 sm[];
    const int z = blockIdx.z;
    const int ri = z & 1;
    const int b = z >> 1;
    if (ri == 0)
        cca_body<5, TILE, NTX>(x, y, out, b, 0, sm);
    else
        cca_body<9, TILE, NTX>(x, y, out, b, 1, sm);
}

extern "C" void kernel_launch(void* const* d_in, const int* in_sizes, int n_in,
                              void* d_out, int out_size) {
    (void)in_sizes; (void)n_in; (void)out_size;
    const float* x = (const float*)d_in[0];
    const float* y = (const float*)d_in[1];
    float* out = (float*)d_out;

    constexpr int TILE = 32, NTX = 8;
    dim3 grid(WW / TILE, HH / TILE, BATCH * 2);
    dim3 block(TILE * NTX);

    // K=9 path: 6 planes of 40 rows x 56-float2 skewed stride
    constexpr int SMX = 6 * 40 * 56 * 8;

    cudaFuncSetAttribute(cca_kernel<TILE, NTX>,
                         cudaFuncAttributeMaxDynamicSharedMemorySize, SMX);

    cca_kernel<TILE, NTX><<<grid, block, SMX>>>(x, y, out);
}

// round 12
// speedup vs baseline: 1.1345x; 1.0103x over previous
#include <cuda_runtime.h>

#define HH 512
#define WW 512
#define CHN 6
#define BATCH 2
#define EPS_F 1e-6f

__device__ __forceinline__ int refl(int i, int n) {
    if (i < 0) i = -i;
    if (i >= n) i = 2 * n - 2 - i;
    return i;
}

// upper-triangle (i<=j) linear index into 21-entry array
__device__ __forceinline__ constexpr int IU(int i, int j) {
    return i * 6 - i * (i - 1) / 2 + (j - i);
}
// lower-triangle (i>=j) linear index into 21-entry array
__device__ __forceinline__ constexpr int IL(int i, int j) {
    return i * (i + 1) / 2 + j;
}

// Per-pixel CCA directly from raw window sums.
__device__ __forceinline__ float cca6(const float* sx, const float* sy,
                                      const float* sxx, const float* syy,
                                      const float* sxy, float inv_n) {
    float xm[6], ym[6];
#pragma unroll
    for (int i = 0; i < 6; i++) { xm[i] = sx[i] * inv_n; ym[i] = sy[i] * inv_n; }

    // Cholesky of cxx and cyy (lower L, 21 entries each); rsqrt-based.
    float Lx[21], Ly[21], ivx[6], ivy[6];
#pragma unroll
    for (int j = 0; j < 6; j++) {
        float dx = fmaf(-xm[j], xm[j], sxx[IU(j, j)] * inv_n) + EPS_F;
        float dy = fmaf(-ym[j], ym[j], syy[IU(j, j)] * inv_n) + EPS_F;
#pragma unroll
        for (int t = 0; t < j; t++) {
            dx = fmaf(-Lx[IL(j, t)], Lx[IL(j, t)], dx);
            dy = fmaf(-Ly[IL(j, t)], Ly[IL(j, t)], dy);
        }
        float rx = rsqrtf(dx), ry = rsqrtf(dy);
        ivx[j] = rx;
        ivy[j] = ry;
        Lx[IL(j, j)] = dx * rx;
        Ly[IL(j, j)] = dy * ry;
#pragma unroll
        for (int i = j + 1; i < 6; i++) {
            float vx = fmaf(-xm[j], xm[i], sxx[IU(j, i)] * inv_n);
            float vy = fmaf(-ym[j], ym[i], syy[IU(j, i)] * inv_n);
#pragma unroll
            for (int t = 0; t < j; t++) {
                vx = fmaf(-Lx[IL(i, t)], Lx[IL(j, t)], vx);
                vy = fmaf(-Ly[IL(i, t)], Ly[IL(j, t)], vy);
            }
            Lx[IL(i, j)] = vx * ivx[j];
            Ly[IL(i, j)] = vy * ivy[j];
        }
    }

    // M = Lx^{-1} * cxy ; only upper triangle (i<=j) needed downstream.
    float MN[21];
#pragma unroll
    for (int j = 0; j < 6; j++) {
#pragma unroll
        for (int i = 0; i <= j; i++) {
            float v = fmaf(-xm[i], ym[j], sxy[i * 6 + j] * inv_n);
#pragma unroll
            for (int t = 0; t < i; t++) v = fmaf(-Lx[IL(i, t)], MN[IU(t, j)], v);
            MN[IU(i, j)] = v * ivx[i];
        }
    }
    // N = M * Ly^{-1}, in place (back-substitution per row).
    float sim = 0.f;
#pragma unroll
    for (int i = 0; i < 6; i++) {
#pragma unroll
        for (int j = 5; j >= i; j--) {
            float v = MN[IU(i, j)];
#pragma unroll
            for (int t = j + 1; t < 6; t++) v = fmaf(-MN[IU(i, t)], Ly[IL(t, j)], v);
            v *= ivy[j];
            MN[IU(i, j)] = v;
            if (j == i) sim += fabsf(v);
        }
    }
    return sim * (1.0f / 6.0f);
}

// Skewed column map: phys(col) = col + (col>>2), row stride PS=56 float2
// (112 words === 16 mod 32) -> conflict-free LDS.64 for the warp's footprint.
__device__ __forceinline__ int skew(int col) { return col + (col >> 2); }

// Compile-time-K body. All plane strides constexpr -> LDS immediate offsets.
template <int K, int TILE, int NTX>
__device__ __forceinline__ void cca_body(
    const float* __restrict__ x, const float* __restrict__ y,
    float* __restrict__ out, int b, int ri, float2* sm) {
    constexpr int R = (K - 1) / 2;
    constexpr int PH = TILE + K - 1;
    constexpr int PW = PH;
    constexpr int PS = 56;       // skewed row stride
    constexpr int CHS = PH * PS; // channel stride (float2 elems), constexpr
    constexpr int RPP = TILE / NTX;
    constexpr float INV_N = 1.0f / (float)(K * K);

    const int tx0 = blockIdx.x * TILE;
    const int ty0 = blockIdx.y * TILE;
    const int tid = threadIdx.x;

    // cooperative load of padded 6-channel (x,y)-packed tile
    for (int idx = tid; idx < 6 * PH * PW; idx += TILE * NTX) {
        int c = idx / (PH * PW);
        int rem = idx - c * (PH * PW);
        int row = rem / PW;
        int col = rem - row * PW;
        int gy = refl(ty0 - R + row, HH);
        int gx = refl(tx0 - R + col, WW);
        size_t gidx = ((size_t)(b * CHN + c) * HH + gy) * WW + gx;
        float2 v;
        v.x = x[gidx];
        v.y = y[gidx];
        sm[c * CHS + row * PS + skew(col)] = v;
    }
    __syncthreads();

    const int txg = tid & (NTX - 1);
    const int ty = tid / NTX;      // output row within tile
    const int c0 = txg * RPP;      // first output col within tile (logical)

    float sx[6], sy[6], sxx[21], syy[21], sxy[36];
#pragma unroll
    for (int i = 0; i < 6; i++) { sx[i] = 0.f; sy[i] = 0.f; }
#pragma unroll
    for (int i = 0; i < 21; i++) { sxx[i] = 0.f; syy[i] = 0.f; }
#pragma unroll
    for (int i = 0; i < 36; i++) sxy[i] = 0.f;

    auto accumAdd = [&](int row, int col) {
        const float2* p = sm + row * PS + skew(col);
        float xv[6], yv[6];
#pragma unroll
        for (int c = 0; c < 6; c++) {
            float2 v = p[c * CHS];
            xv[c] = v.x;
            yv[c] = v.y;
        }
#pragma unroll
        for (int i = 0; i < 6; i++) { sx[i] += xv[i]; sy[i] += yv[i]; }
        int t = 0;
#pragma unroll
        for (int i = 0; i < 6; i++)
#pragma unroll
            for (int j = i; j < 6; j++, t++) {
                sxx[t] = fmaf(xv[i], xv[j], sxx[t]);
                syy[t] = fmaf(yv[i], yv[j], syy[t]);
            }
#pragma unroll
        for (int i = 0; i < 6; i++)
#pragma unroll
            for (int j = 0; j < 6; j++)
                sxy[i * 6 + j] = fmaf(xv[i], yv[j], sxy[i * 6 + j]);
    };

    // Fused slide update: ALL 12 LDS issued first (sub point + add point),
    // then 180 FMAs cover their latency.
    auto accumSlide = [&](int row, int colS, int colA) {
        const float2* ps = sm + row * PS + skew(colS);
        const float2* pa = sm + row * PS + skew(colA);
        float xs[6], ys[6], xa[6], ya[6];
#pragma unroll
        for (int c = 0; c < 6; c++) {
            float2 v = ps[c * CHS];
            xs[c] = v.x;
            ys[c] = v.y;
        }
#pragma unroll
        for (int c = 0; c < 6; c++) {
            float2 v = pa[c * CHS];
            xa[c] = v.x;
            ya[c] = v.y;
        }
#pragma unroll
        for (int i = 0; i < 6; i++) {
            sx[i] += (xa[i] - xs[i]);
            sy[i] += (ya[i] - ys[i]);
        }
        int t = 0;
#pragma unroll
        for (int i = 0; i < 6; i++)
#pragma unroll
            for (int j = i; j < 6; j++, t++) {
                sxx[t] = fmaf(xa[i], xa[j], sxx[t]);
                sxx[t] = fmaf(-xs[i], xs[j], sxx[t]);
                syy[t] = fmaf(ya[i], ya[j], syy[t]);
                syy[t] = fmaf(-ys[i], ys[j], syy[t]);
            }
#pragma unroll
        for (int i = 0; i < 6; i++)
#pragma unroll
            for (int j = 0; j < 6; j++) {
                sxy[i * 6 + j] = fmaf(xa[i], ya[j], sxy[i * 6 + j]);
                sxy[i * 6 + j] = fmaf(-xs[i], ys[j], sxy[i * 6 + j]);
            }
    };

    // initial full window for first pixel
#pragma unroll 1
    for (int r = 0; r < K; ++r)
#pragma unroll 3
        for (int c = 0; c < K; ++c) accumAdd(ty + r, c0 + c);

    const int gy = ty0 + ty;
    {
        float sim = cca6(sx, sy, sxx, syy, sxy, INV_N);
        out[(((size_t)b * HH + gy) * WW + (tx0 + c0)) * 2 + ri] = sim;
    }

#pragma unroll 1
    for (int p = 1; p < RPP; ++p) {
#pragma unroll 3
        for (int r = 0; r < K; ++r)
            accumSlide(ty + r, c0 + p - 1, c0 + p - 1 + K);
        float sim = cca6(sx, sy, sxx, syy, sxy, INV_N);
        out[(((size_t)b * HH + gy) * WW + (tx0 + c0 + p)) * 2 + ri] = sim;
    }
}

// Single merged launch. z in {0,1}: K=9 batches (expensive, scheduled first);
// z in {2,3}: K=5 batches (cheap tail shortens the final partial wave).
template <int TILE, int NTX>
__global__ __launch_bounds__(TILE* NTX, 2) void cca_kernel(
    const float* __restrict__ x, const float* __restrict__ y,
    float* __restrict__ out) {
    extern __shared__ float2 sm[];
    const int z = blockIdx.z;
    if (z < 2)
        cca_body<9, TILE, NTX>(x, y, out, z, 1, sm);
    else
        cca_body<5, TILE, NTX>(x, y, out, z - 2, 0, sm);
}

extern "C" void kernel_launch(void* const* d_in, const int* in_sizes, int n_in,
                              void* d_out, int out_size) {
    (void)in_sizes; (void)n_in; (void)out_size;
    const float* x = (const float*)d_in[0];
    const float* y = (const float*)d_in[1];
    float* out = (float*)d_out;

    constexpr int TILE = 32, NTX = 8;
    dim3 grid(WW / TILE, HH / TILE, BATCH * 2);
    dim3 block(TILE * NTX);

    // K=9 path: 6 planes of 40 rows x 56-float2 skewed stride
    constexpr int SMX = 6 * 40 * 56 * 8;

    cudaFuncSetAttribute(cca_kernel<TILE, NTX>,
                         cudaFuncAttributeMaxDynamicSharedMemorySize, SMX);

    cca_kernel<TILE, NTX><<<grid, block, SMX>>>(x, y, out);
}